// round 1
// baseline (speedup 1.0000x reference)
#include <cuda_runtime.h>

// y[b] = a_0 + sum_k bk[k] * tanh( sum_z ck[k][z]*z[b][z] + dk[k] )
// B = 2097152, Z = 16, K = 64.
// Compute-bound in fp32 FMA -> use packed fma.rn.f32x2 across TWO batch rows
// per thread; ck/dk/bk staged in shared pre-duplicated as {c,c} pairs so the
// packed operand is one broadcast LDS. tanh via MUFU (tanh.approx.f32).

#define KK 64
#define ZZ 16
#define TPB 256
#define ROWS_PER_THREAD 2

typedef unsigned long long u64t;

__device__ __forceinline__ u64t pack2(float lo, float hi) {
    u64t r; asm("mov.b64 %0, {%1, %2};" : "=l"(r) : "f"(lo), "f"(hi)); return r;
}
__device__ __forceinline__ void unpack2(u64t v, float& lo, float& hi) {
    asm("mov.b64 {%0, %1}, %2;" : "=f"(lo), "=f"(hi) : "l"(v));
}
__device__ __forceinline__ u64t fma2(u64t a, u64t b, u64t c) {
    u64t d; asm("fma.rn.f32x2 %0, %1, %2, %3;" : "=l"(d) : "l"(a), "l"(b), "l"(c)); return d;
}
__device__ __forceinline__ u64t add2(u64t a, u64t b) {
    u64t d; asm("add.rn.f32x2 %0, %1, %2;" : "=l"(d) : "l"(a), "l"(b)); return d;
}
__device__ __forceinline__ float tanha(float x) {
    float y; asm("tanh.approx.f32 %0, %1;" : "=f"(y) : "f"(x)); return y;
}

__global__ __launch_bounds__(TPB)
void mave_kernel(const float* __restrict__ z,
                 const float* __restrict__ a0p,
                 const float* __restrict__ bk,
                 const float* __restrict__ ck,
                 const float* __restrict__ dk,
                 float* __restrict__ out)
{
    // Shared: ck duplicated as {c,c} f32x2 (64 k x 16 z), dk/bk duplicated.
    __shared__ u64t sC[KK * ZZ];   // 8 KB, sC[k*ZZ + z] = {ck[k][z], ck[k][z]}
    __shared__ u64t sD[KK];        // {dk,dk}
    __shared__ u64t sB[KK];        // {bk,bk}

    const int tid = threadIdx.x;
    #pragma unroll
    for (int i = tid; i < KK * ZZ; i += TPB) {
        float c = ck[i];
        sC[i] = pack2(c, c);
    }
    if (tid < KK) {
        float d = dk[tid]; sD[tid] = pack2(d, d);
        float b = bk[tid]; sB[tid] = pack2(b, b);
    }
    __syncthreads();

    const float a0 = a0p[0];

    // Each thread handles 2 consecutive rows.
    const long long g   = (long long)blockIdx.x * TPB + tid;
    const long long row = g * ROWS_PER_THREAD;

    // Load both rows' z vectors (2 x 16 floats = 8 float4).
    const float4* zp = (const float4*)(z + row * ZZ);
    float4 r0[4], r1[4];
    #pragma unroll
    for (int i = 0; i < 4; i++) r0[i] = zp[i];
    #pragma unroll
    for (int i = 0; i < 4; i++) r1[i] = zp[4 + i];

    // Pack zz[z] = {z_row0[z], z_row1[z]}.
    u64t zz[ZZ];
    #pragma unroll
    for (int i = 0; i < 4; i++) {
        zz[4*i + 0] = pack2(((const float*)&r0[i])[0], ((const float*)&r1[i])[0]);
        zz[4*i + 1] = pack2(((const float*)&r0[i])[1], ((const float*)&r1[i])[1]);
        zz[4*i + 2] = pack2(((const float*)&r0[i])[2], ((const float*)&r1[i])[2]);
        zz[4*i + 3] = pack2(((const float*)&r0[i])[3], ((const float*)&r1[i])[3]);
    }

    u64t y2 = pack2(0.f, 0.f);

    #pragma unroll 4
    for (int k = 0; k < KK; k++) {
        const u64t* cr = &sC[k * ZZ];
        // Two independent accumulator chains to break the RAW chain (lat 4, rt 2).
        u64t accA = sD[k];
        u64t accB = pack2(0.f, 0.f);
        #pragma unroll
        for (int zi = 0; zi < ZZ; zi += 2) {
            accA = fma2(cr[zi],     zz[zi],     accA);
            accB = fma2(cr[zi + 1], zz[zi + 1], accB);
        }
        u64t s = add2(accA, accB);
        float s0, s1;
        unpack2(s, s0, s1);
        u64t h2 = pack2(tanha(s0), tanha(s1));
        y2 = fma2(sB[k], h2, y2);
    }

    float y0, y1;
    unpack2(y2, y0, y1);
    float2 o = make_float2(a0 + y0, a0 + y1);
    *(float2*)(out + row) = o;
}

extern "C" void kernel_launch(void* const* d_in, const int* in_sizes, int n_in,
                              void* d_out, int out_size) {
    const float* z  = (const float*)d_in[0];
    const float* a0 = (const float*)d_in[1];
    const float* bk = (const float*)d_in[2];
    const float* ck = (const float*)d_in[3];
    const float* dk = (const float*)d_in[4];
    float* out = (float*)d_out;

    const long long B = (long long)in_sizes[0] / ZZ;  // 2097152
    const int threads = (int)(B / ROWS_PER_THREAD);
    const int blocks  = (threads + TPB - 1) / TPB;    // 4096
    mave_kernel<<<blocks, TPB>>>(z, a0, bk, ck, dk, out);
}

// round 2
// speedup vs baseline: 1.3846x; 1.3846x over previous
#include <cuda_runtime.h>

// y[b] = a_0 + sum_k bk[k] * tanh( sum_z ck[k][z]*z[b][z] + dk[k] )
// B = 2097152, Z = 16, K = 64.
// FMA floor ~61us (f32x2 @ rt2/SMSP). Round-1 was L1-bound (LDS stream).
// Fix: 4 rows/thread (2 f32x2 row-pairs share every ck LDS) + LDS.128 on
// duplicated {c,c} pairs + fused {d,d,b,b} float4 -> ~4x fewer LDS/row.

#define KK 64
#define ZZ 16
#define TPB 128
#define RPT 4   // rows per thread (2 packed pairs)

typedef unsigned long long u64t;

__device__ __forceinline__ u64t pack2(float lo, float hi) {
    u64t r; asm("mov.b64 %0, {%1, %2};" : "=l"(r) : "f"(lo), "f"(hi)); return r;
}
__device__ __forceinline__ void unpack2(u64t v, float& lo, float& hi) {
    asm("mov.b64 {%0, %1}, %2;" : "=f"(lo), "=f"(hi) : "l"(v));
}
__device__ __forceinline__ u64t fma2(u64t a, u64t b, u64t c) {
    u64t d; asm("fma.rn.f32x2 %0, %1, %2, %3;" : "=l"(d) : "l"(a), "l"(b), "l"(c)); return d;
}
__device__ __forceinline__ u64t add2(u64t a, u64t b) {
    u64t d; asm("add.rn.f32x2 %0, %1, %2;" : "=l"(d) : "l"(a), "l"(b)); return d;
}
__device__ __forceinline__ float tanha(float x) {
    float y; asm("tanh.approx.f32 %0, %1;" : "=f"(y) : "f"(x)); return y;
}

__global__ __launch_bounds__(TPB)
void mave_kernel(const float* __restrict__ z,
                 const float* __restrict__ a0p,
                 const float* __restrict__ bk,
                 const float* __restrict__ ck,
                 const float* __restrict__ dk,
                 float* __restrict__ out)
{
    // sC[k*16+z] = {ck[k][z], ck[k][z]} (8 KB, 16B-aligned for LDS.128)
    __shared__ __align__(16) u64t sC[KK * ZZ];
    __shared__ __align__(16) float4 sDB[KK];   // {d, d, b, b}

    const int tid = threadIdx.x;
    #pragma unroll
    for (int i = tid; i < KK * ZZ; i += TPB) {
        float c = ck[i];
        sC[i] = pack2(c, c);
    }
    if (tid < KK) {
        float d = dk[tid], b = bk[tid];
        sDB[tid] = make_float4(d, d, b, b);
    }
    __syncthreads();

    const float a0 = a0p[0];

    const long long g   = (long long)blockIdx.x * TPB + tid;
    const long long row = g * RPT;

    // Load 4 rows of z (16 floats each = 4 float4 per row).
    const float4* zp = (const float4*)(z + row * ZZ);
    float4 r0[4], r1[4], r2[4], r3[4];
    #pragma unroll
    for (int i = 0; i < 4; i++) r0[i] = zp[i];
    #pragma unroll
    for (int i = 0; i < 4; i++) r1[i] = zp[4 + i];
    #pragma unroll
    for (int i = 0; i < 4; i++) r2[i] = zp[8 + i];
    #pragma unroll
    for (int i = 0; i < 4; i++) r3[i] = zp[12 + i];

    // zz0[z] = {row0[z], row1[z]}, zz1[z] = {row2[z], row3[z]}
    u64t zz0[ZZ], zz1[ZZ];
    #pragma unroll
    for (int i = 0; i < 4; i++) {
        const float* a = (const float*)&r0[i];
        const float* b = (const float*)&r1[i];
        const float* c = (const float*)&r2[i];
        const float* d = (const float*)&r3[i];
        #pragma unroll
        for (int j = 0; j < 4; j++) {
            zz0[4*i + j] = pack2(a[j], b[j]);
            zz1[4*i + j] = pack2(c[j], d[j]);
        }
    }

    const u64t zero = pack2(0.f, 0.f);
    u64t y0 = zero, y1 = zero;

    #pragma unroll 4
    for (int k = 0; k < KK; k++) {
        // 16 {c,c} pairs via 8 LDS.128
        u64t c[ZZ];
        const ulonglong2* cr = (const ulonglong2*)&sC[k * ZZ];
        #pragma unroll
        for (int j = 0; j < 8; j++) {
            ulonglong2 v = cr[j];
            c[2*j] = v.x; c[2*j + 1] = v.y;
        }
        float4 db = sDB[k];                  // 1 LDS.128
        u64t dd = pack2(db.x, db.y);
        u64t bb = pack2(db.z, db.w);

        // 2 chains per pair x 2 pairs = 4-way ILP, chain depth 8
        u64t aA0 = dd, aB0 = zero, aA1 = dd, aB1 = zero;
        #pragma unroll
        for (int zi = 0; zi < ZZ; zi += 2) {
            aA0 = fma2(c[zi],     zz0[zi],     aA0);
            aB0 = fma2(c[zi + 1], zz0[zi + 1], aB0);
            aA1 = fma2(c[zi],     zz1[zi],     aA1);
            aB1 = fma2(c[zi + 1], zz1[zi + 1], aB1);
        }
        u64t s0 = add2(aA0, aB0);
        u64t s1 = add2(aA1, aB1);
        float s0l, s0h, s1l, s1h;
        unpack2(s0, s0l, s0h);
        unpack2(s1, s1l, s1h);
        u64t h0 = pack2(tanha(s0l), tanha(s0h));
        u64t h1 = pack2(tanha(s1l), tanha(s1h));
        y0 = fma2(bb, h0, y0);
        y1 = fma2(bb, h1, y1);
    }

    float y0l, y0h, y1l, y1h;
    unpack2(y0, y0l, y0h);
    unpack2(y1, y1l, y1h);
    float4 o = make_float4(a0 + y0l, a0 + y0h, a0 + y1l, a0 + y1h);
    *(float4*)(out + row) = o;
}

extern "C" void kernel_launch(void* const* d_in, const int* in_sizes, int n_in,
                              void* d_out, int out_size) {
    const float* z  = (const float*)d_in[0];
    const float* a0 = (const float*)d_in[1];
    const float* bk = (const float*)d_in[2];
    const float* ck = (const float*)d_in[3];
    const float* dk = (const float*)d_in[4];
    float* out = (float*)d_out;

    const long long B = (long long)in_sizes[0] / ZZ;   // 2097152
    const long long threads = B / RPT;                  // 524288
    const int blocks = (int)((threads + TPB - 1) / TPB);  // 4096
    mave_kernel<<<blocks, TPB>>>(z, a0, bk, ck, dk, out);
}

// round 3
// speedup vs baseline: 1.5456x; 1.1163x over previous
#include <cuda_runtime.h>

// y[b] = a_0 + sum_k bk[k] * tanh( sum_z ck[k][z]*z[b][z] + dk[k] )
// B = 2097152, Z = 16, K = 64.
// Round-2 was L1-bound: duplicated {c,c} f32x2 operands deliver 2x bytes
// (smem wavefronts count per-lane RF bytes, broadcast included).
// Round-3: pack along Z instead. acc = sum_j {c2j*z2j, c2j+1*z2j+1}, one
// horizontal FADD per row. ck loaded in natural layout (4x LDS.128 per k,
// shared by 4 rows). dk pre-packed as {d,0} -> consumed as addend of the
// first FMA2 (no init movs). FMA pipe becomes the binder (~72us model).

#define KK 64
#define ZZ 16
#define TPB 128
#define RPT 4   // rows per thread (must divide B=2^21)

typedef unsigned long long u64t;

__device__ __forceinline__ u64t pack2(float lo, float hi) {
    u64t r; asm("mov.b64 %0, {%1, %2};" : "=l"(r) : "f"(lo), "f"(hi)); return r;
}
__device__ __forceinline__ void unpack2(u64t v, float& lo, float& hi) {
    asm("mov.b64 {%0, %1}, %2;" : "=f"(lo), "=f"(hi) : "l"(v));
}
__device__ __forceinline__ u64t fma2(u64t a, u64t b, u64t c) {
    u64t d; asm("fma.rn.f32x2 %0, %1, %2, %3;" : "=l"(d) : "l"(a), "l"(b), "l"(c)); return d;
}
__device__ __forceinline__ float tanha(float x) {
    float y; asm("tanh.approx.f32 %0, %1;" : "=f"(y) : "f"(x)); return y;
}

__global__ __launch_bounds__(TPB)
void mave_kernel(const float* __restrict__ z,
                 const float* __restrict__ a0p,
                 const float* __restrict__ bk,
                 const float* __restrict__ ck,
                 const float* __restrict__ dk,
                 float* __restrict__ out)
{
    // ck in natural layout, viewed as f32x2 pairs along z: sC[k*8 + j] = {c[2j], c[2j+1]}
    __shared__ __align__(16) u64t sC[KK * ZZ / 2];   // 4 KB
    __shared__ __align__(16) u64t sD2[KK];           // {d, 0}
    __shared__ float sB[KK];                          // b

    const int tid = threadIdx.x;
    #pragma unroll
    for (int i = tid; i < KK * ZZ / 2; i += TPB) {
        const float2 c2 = ((const float2*)ck)[i];
        sC[i] = pack2(c2.x, c2.y);
    }
    if (tid < KK) {
        sD2[tid] = pack2(dk[tid], 0.f);
        sB[tid]  = bk[tid];
    }
    __syncthreads();

    const float a0 = a0p[0];

    const long long g   = (long long)blockIdx.x * TPB + tid;
    const long long row = g * RPT;

    // Load 4 rows of z; keep packed along z: zz[r][j] = {z_r[2j], z_r[2j+1]}.
    u64t zz[RPT][ZZ / 2];
    const float4* zp = (const float4*)(z + row * ZZ);
    #pragma unroll
    for (int r = 0; r < RPT; r++) {
        #pragma unroll
        for (int i = 0; i < 4; i++) {
            float4 v = zp[r * 4 + i];
            zz[r][2*i + 0] = pack2(v.x, v.y);
            zz[r][2*i + 1] = pack2(v.z, v.w);
        }
    }

    float y[RPT];
    #pragma unroll
    for (int r = 0; r < RPT; r++) y[r] = 0.f;

    #pragma unroll 4
    for (int k = 0; k < KK; k++) {
        // 8 {c,c'} pairs via 4 LDS.128 (natural layout, no duplication)
        u64t c[ZZ / 2];
        const ulonglong2* cr = (const ulonglong2*)&sC[k * (ZZ / 2)];
        #pragma unroll
        for (int j = 0; j < 4; j++) {
            ulonglong2 v = cr[j];
            c[2*j] = v.x; c[2*j + 1] = v.y;
        }
        const u64t dd = sD2[k];   // {d, 0}
        const float b = sB[k];

        // One 8-deep FMA2 chain per row; 4 independent chains give the ILP.
        u64t acc[RPT];
        #pragma unroll
        for (int r = 0; r < RPT; r++) acc[r] = fma2(c[0], zz[r][0], dd);
        #pragma unroll
        for (int j = 1; j < ZZ / 2; j++) {
            #pragma unroll
            for (int r = 0; r < RPT; r++) acc[r] = fma2(c[j], zz[r][j], acc[r]);
        }
        #pragma unroll
        for (int r = 0; r < RPT; r++) {
            float lo, hi;
            unpack2(acc[r], lo, hi);
            float s = lo + hi;            // full dot + d
            y[r] = fmaf(b, tanha(s), y[r]);
        }
    }

    float4 o = make_float4(a0 + y[0], a0 + y[1], a0 + y[2], a0 + y[3]);
    *(float4*)(out + row) = o;
}

extern "C" void kernel_launch(void* const* d_in, const int* in_sizes, int n_in,
                              void* d_out, int out_size) {
    const float* z  = (const float*)d_in[0];
    const float* a0 = (const float*)d_in[1];
    const float* bk = (const float*)d_in[2];
    const float* ck = (const float*)d_in[3];
    const float* dk = (const float*)d_in[4];
    float* out = (float*)d_out;

    const long long B = (long long)in_sizes[0] / ZZ;     // 2097152
    const long long threads = B / RPT;                    // 524288
    const int blocks = (int)((threads + TPB - 1) / TPB);  // 4096
    mave_kernel<<<blocks, TPB>>>(z, a0, bk, ck, dk, out);
}

// round 5
// speedup vs baseline: 1.5829x; 1.0241x over previous
#include <cuda_runtime.h>

// y[b] = a_0 + sum_k bk[k] * tanh( sum_z ck[k][z]*z[b][z] + dk[k] )
// B = 2097152, Z = 16, K = 64.
// Round-3 was issue/latency-bound (occ 29%, issue 45%): LDS lat + MUFU stalls
// eat FMA slots. Round-4: ck/dk/bk are warp-uniform -> move them to the
// CONSTANT port (LDC, separate from L1/LSU), populated via graph-capturable
// cudaMemcpyToSymbolAsync D2D in kernel_launch. No smem, no __syncthreads.

#define KK 64
#define ZZ 16
#define TPB 128
#define RPT 4   // rows per thread (must divide B = 2^21)

typedef unsigned long long u64t;

__constant__ float cC[KK * ZZ];   // ck, natural layout (z-pairs contiguous)
__constant__ float cD[KK];
__constant__ float cB[KK];
__constant__ float cA0[1];

__device__ __forceinline__ u64t pack2(float lo, float hi) {
    u64t r; asm("mov.b64 %0, {%1, %2};" : "=l"(r) : "f"(lo), "f"(hi)); return r;
}
__device__ __forceinline__ void unpack2(u64t v, float& lo, float& hi) {
    asm("mov.b64 {%0, %1}, %2;" : "=f"(lo), "=f"(hi) : "l"(v));
}
__device__ __forceinline__ u64t fma2(u64t a, u64t b, u64t c) {
    u64t d; asm("fma.rn.f32x2 %0, %1, %2, %3;" : "=l"(d) : "l"(a), "l"(b), "l"(c)); return d;
}
__device__ __forceinline__ float tanha(float x) {
    float y; asm("tanh.approx.f32 %0, %1;" : "=f"(y) : "f"(x)); return y;
}

__global__ __launch_bounds__(TPB)
void mave_kernel(const float* __restrict__ z, float* __restrict__ out)
{
    const int tid = threadIdx.x;
    const long long g   = (long long)blockIdx.x * TPB + tid;
    const long long row = g * RPT;

    // Load 4 rows of z, packed along z: zz[r][j] = {z_r[2j], z_r[2j+1]}.
    u64t zz[RPT][ZZ / 2];
    const float4* zp = (const float4*)(z + row * ZZ);
    #pragma unroll
    for (int r = 0; r < RPT; r++) {
        #pragma unroll
        for (int i = 0; i < 4; i++) {
            float4 v = zp[r * 4 + i];
            zz[r][2*i + 0] = pack2(v.x, v.y);
            zz[r][2*i + 1] = pack2(v.z, v.w);
        }
    }

    float y[RPT];
    #pragma unroll
    for (int r = 0; r < RPT; r++) y[r] = 0.f;

    const u64t* cpair = (const u64t*)cC;   // 8B-aligned z-pairs

    #pragma unroll 4
    for (int k = 0; k < KK; k++) {
        // 8 {c2j, c2j+1} pairs via LDC.64 (constant port, broadcast-native)
        u64t c[ZZ / 2];
        #pragma unroll
        for (int j = 0; j < ZZ / 2; j++) c[j] = cpair[k * (ZZ / 2) + j];

        const u64t dd = pack2(cD[k], 0.f);   // {d, 0} addend for first fma2
        const float b = cB[k];

        // One 8-deep FMA2 chain per row; 4 independent chains give the ILP.
        u64t acc[RPT];
        #pragma unroll
        for (int r = 0; r < RPT; r++) acc[r] = fma2(c[0], zz[r][0], dd);
        #pragma unroll
        for (int j = 1; j < ZZ / 2; j++) {
            #pragma unroll
            for (int r = 0; r < RPT; r++) acc[r] = fma2(c[j], zz[r][j], acc[r]);
        }
        #pragma unroll
        for (int r = 0; r < RPT; r++) {
            float lo, hi;
            unpack2(acc[r], lo, hi);
            y[r] = fmaf(b, tanha(lo + hi), y[r]);
        }
    }

    const float a0 = cA0[0];
    float4 o = make_float4(a0 + y[0], a0 + y[1], a0 + y[2], a0 + y[3]);
    *(float4*)(out + row) = o;
}

extern "C" void kernel_launch(void* const* d_in, const int* in_sizes, int n_in,
                              void* d_out, int out_size) {
    const float* z  = (const float*)d_in[0];
    // Populate constant bank from device inputs (D2D memcpy: graph-capturable).
    cudaMemcpyToSymbolAsync(cA0, d_in[1], sizeof(float),          0, cudaMemcpyDeviceToDevice);
    cudaMemcpyToSymbolAsync(cB,  d_in[2], KK * sizeof(float),     0, cudaMemcpyDeviceToDevice);
    cudaMemcpyToSymbolAsync(cC,  d_in[3], KK * ZZ * sizeof(float),0, cudaMemcpyDeviceToDevice);
    cudaMemcpyToSymbolAsync(cD,  d_in[4], KK * sizeof(float),     0, cudaMemcpyDeviceToDevice);

    float* out = (float*)d_out;
    const long long B = (long long)in_sizes[0] / ZZ;      // 2097152
    const long long threads = B / RPT;                     // 524288
    const int blocks = (int)((threads + TPB - 1) / TPB);   // 4096
    mave_kernel<<<blocks, TPB>>>(z, out);
}